// round 15
// baseline (speedup 1.0000x reference)
#include <cuda_runtime.h>
#include <cuda_bf16.h>
#include <math.h>
#include <stdint.h>

// Problem constants
#define Bn   8
#define Tn   1024
#define Cn   1024
#define Hn   16
#define HSn  64
#define NBn  63
#define WINn 128
#define EPSf 1e-5f

// ---------------- scratch (device globals; no allocation) ----------------
__device__ float g_qkv [Bn * Tn * 3 * Cn];        // [B,T,3C]
__device__ float g_kc  [Bn * Hn * NBn * HSn];
__device__ float g_vc  [Bn * Hn * NBn * HSn];
__device__ float g_loc [Bn * Tn * Cn];
__device__ float g_cmp [Bn * Tn * Cn];
__device__ float g_comb[Bn * Tn * Cn];
__device__ float g_gates[Bn * 2];
__device__ float g_kt  [Bn * Hn * HSn * Tn];      // transposed K heads [bh][i][t]
__device__ float g_vt  [Bn * Hn * HSn * Tn];
// bf16 split buffers (reused between the two GEMMs)
__device__ __nv_bfloat16 g_ah[Bn * Tn * Cn];      // 8M
__device__ __nv_bfloat16 g_al[Bn * Tn * Cn];
__device__ __nv_bfloat16 g_bh[3 * Cn * Cn];       // 3M (covers both weight mats)
__device__ __nv_bfloat16 g_bl[3 * Cn * Cn];

// ================= helpers =================
__device__ __forceinline__ uint32_t smem_to_u32(const void* p) {
    uint32_t a;
    asm("{ .reg .u64 t; cvta.to.shared.u64 t, %1; cvt.u32.u64 %0, t; }" : "=r"(a) : "l"(p));
    return a;
}
__device__ __forceinline__ void cp16(uint32_t dst, const void* src) {
    asm volatile("cp.async.cg.shared.global [%0], [%1], 16;" :: "r"(dst), "l"(src) : "memory");
}
__device__ __forceinline__ void ldsm_x4(uint32_t& r0, uint32_t& r1, uint32_t& r2, uint32_t& r3,
                                        uint32_t addr) {
    asm volatile("ldmatrix.sync.aligned.m8n8.x4.shared.b16 {%0,%1,%2,%3}, [%4];"
                 : "=r"(r0), "=r"(r1), "=r"(r2), "=r"(r3) : "r"(addr));
}
__device__ __forceinline__ void mma_bf16(float* c, const uint32_t* a, const uint32_t* b) {
    asm volatile(
        "mma.sync.aligned.m16n8k16.row.col.f32.bf16.bf16.f32 "
        "{%0,%1,%2,%3}, {%4,%5,%6,%7}, {%8,%9}, {%0,%1,%2,%3};"
        : "+f"(c[0]), "+f"(c[1]), "+f"(c[2]), "+f"(c[3])
        : "r"(a[0]), "r"(a[1]), "r"(a[2]), "r"(a[3]), "r"(b[0]), "r"(b[1]));
}
// swizzled byte offset inside a [128 rows][64 bf16] tile (128B rows, 8x16B chunks)
__device__ __forceinline__ uint32_t swz64(int row, int chunk) {
    return (uint32_t)(row * 128 + ((chunk ^ (row & 7)) << 4));
}

// ================= split fp32 -> (hi, lo) bf16 =================
__global__ __launch_bounds__(256)
void split_bf16_kernel(const float4* __restrict__ in, __nv_bfloat162* __restrict__ hi,
                       __nv_bfloat162* __restrict__ lo, int n4)
{
    int i = blockIdx.x * 256 + threadIdx.x;
    if (i >= n4) return;
    float4 v = in[i];
    __nv_bfloat16 h0 = __float2bfloat16(v.x), h1 = __float2bfloat16(v.y);
    __nv_bfloat16 h2 = __float2bfloat16(v.z), h3 = __float2bfloat16(v.w);
    __nv_bfloat16 l0 = __float2bfloat16(v.x - __bfloat162float(h0));
    __nv_bfloat16 l1 = __float2bfloat16(v.y - __bfloat162float(h1));
    __nv_bfloat16 l2 = __float2bfloat16(v.z - __bfloat162float(h2));
    __nv_bfloat16 l3 = __float2bfloat16(v.w - __bfloat162float(h3));
    hi[2 * i]     = __halves2bfloat162(h0, h1);
    hi[2 * i + 1] = __halves2bfloat162(h2, h3);
    lo[2 * i]     = __halves2bfloat162(l0, l1);
    lo[2 * i + 1] = __halves2bfloat162(l2, l3);
}

// ================= mma.sync bf16 GEMM =================
// C[m,n] = sum_k A[m,k]*B[n,k], fp32 out, via Ah*Bh + Ah*Bl + Al*Bh.
// CTA tile 128x128, BK=64, 8 warps (2x4), warp tile 64x32, 2-stage cp.async.
// dynamic smem: 2 stages x (16KB A + 16KB B) = 64 KB.
#define GEMM_SMEM_BYTES 65536
__global__ __launch_bounds__(256, 2)
void gemm_bf16_mma(const __nv_bfloat16* __restrict__ Ah, const __nv_bfloat16* __restrict__ Al,
                   const __nv_bfloat16* __restrict__ Bh, const __nv_bfloat16* __restrict__ Bl,
                   float* __restrict__ C, int N, int K)
{
    extern __shared__ __align__(16) char dsm[];

    const int tid = threadIdx.x;
    const int warp = tid >> 5, lane = tid & 31;
    const int wm = warp >> 2;       // 0..1 -> m offset wm*64
    const int wn = warp & 3;        // 0..3 -> n offset wn*32

    const int m0 = blockIdx.y * 128;
    const int n0 = blockIdx.x * 128;

    const __nv_bfloat16* Aps[3] = { Ah, Ah, Al };
    const __nv_bfloat16* Bps[3] = { Bh, Bl, Bh };

    const int sp = K >> 6;               // slabs per pass
    const int total_slabs = 3 * sp;

    const uint32_t sbase = smem_to_u32(dsm);
    // stage st: A at st*32768, B at st*32768 + 16384
    const int lrow = tid >> 1;                 // 0..127
    const int lch0 = (tid & 1) << 2;           // 0 or 4

    auto load_slab = [&](int stage, int slab) {
        const int pass = slab / sp;
        const int k0 = (slab - pass * sp) << 6;
        const __nv_bfloat16* Ap = Aps[pass] + (size_t)(m0 + lrow) * K + k0;
        const __nv_bfloat16* Bp = Bps[pass] + (size_t)(n0 + lrow) * K + k0;
        const uint32_t aB = sbase + stage * 32768;
        const uint32_t bB = aB + 16384;
#pragma unroll
        for (int c = 0; c < 4; ++c) {
            const int ch = lch0 + c;
            cp16(aB + swz64(lrow, ch), Ap + ch * 8);
            cp16(bB + swz64(lrow, ch), Bp + ch * 8);
        }
        asm volatile("cp.async.commit_group;" ::: "memory");
    };

    float acc[4][4][4];
#pragma unroll
    for (int i = 0; i < 4; ++i)
#pragma unroll
        for (int j = 0; j < 4; ++j)
#pragma unroll
            for (int q = 0; q < 4; ++q) acc[i][j][q] = 0.f;

    load_slab(0, 0);
    load_slab(1, 1);

    const int l16 = lane & 15, lhi = lane >> 4;      // A ldmatrix addressing
    const int l8 = lane & 7, grp = lane >> 3;        // B ldmatrix addressing

    for (int s = 0; s < total_slabs; ++s) {
        if (s == total_slabs - 1) asm volatile("cp.async.wait_group 0;" ::: "memory");
        else                      asm volatile("cp.async.wait_group 1;" ::: "memory");
        __syncthreads();

        const int st = s & 1;
        const uint32_t aB = sbase + st * 32768;
        const uint32_t bB = aB + 16384;
#pragma unroll
        for (int j = 0; j < 4; ++j) {                 // four k16 steps per slab
            uint32_t af[4][4];
#pragma unroll
            for (int mt = 0; mt < 4; ++mt) {
                const int row = wm * 64 + mt * 16 + l16;
                ldsm_x4(af[mt][0], af[mt][1], af[mt][2], af[mt][3],
                        aB + swz64(row, 2 * j + lhi));
            }
            uint32_t bfr[4][2];
#pragma unroll
            for (int g = 0; g < 2; ++g) {
                const int row = wn * 32 + g * 16 + ((grp >> 1) << 3) + l8;
                uint32_t r0, r1, r2, r3;
                ldsm_x4(r0, r1, r2, r3, bB + swz64(row, 2 * j + (grp & 1)));
                bfr[g * 2 + 0][0] = r0; bfr[g * 2 + 0][1] = r1;
                bfr[g * 2 + 1][0] = r2; bfr[g * 2 + 1][1] = r3;
            }
#pragma unroll
            for (int mt = 0; mt < 4; ++mt)
#pragma unroll
                for (int nt = 0; nt < 4; ++nt)
                    mma_bf16(acc[mt][nt], af[mt], bfr[nt]);
        }
        __syncthreads();
        if (s + 2 < total_slabs) load_slab(st, s + 2);
    }

    // epilogue
    const int gr = lane >> 2, gc = (lane & 3) << 1;
#pragma unroll
    for (int mt = 0; mt < 4; ++mt) {
#pragma unroll
        for (int nt = 0; nt < 4; ++nt) {
            float* p0 = C + (size_t)(m0 + wm * 64 + mt * 16 + gr) * N
                         + n0 + wn * 32 + nt * 8 + gc;
            float* p1 = p0 + (size_t)8 * N;
            *(float2*)p0 = make_float2(acc[mt][nt][0], acc[mt][nt][1]);
            *(float2*)p1 = make_float2(acc[mt][nt][2], acc[mt][nt][3]);
        }
    }
}

// ---------------- transpose K/V heads: qkv -> [bh][i][t] ----------------
__global__ __launch_bounds__(256)
void transpose_kv_kernel(const float* __restrict__ qkv,
                         float* __restrict__ kt, float* __restrict__ vt)
{
    __shared__ float tile[32][33];
    const int z = blockIdx.z;
    const int sel = z & 1, bh = z >> 1;
    const int b = bh >> 4, h = bh & 15;
    const float* src = qkv + (size_t)b * Tn * 3072 + 1024 + sel * 1024 + h * 64;
    const int t0 = blockIdx.x * 32, i0 = blockIdx.y * 32;
    const int tx = threadIdx.x & 31, ty = threadIdx.x >> 5;   // 32 x 8

#pragma unroll
    for (int r = 0; r < 32; r += 8)
        tile[ty + r][tx] = src[(size_t)(t0 + ty + r) * 3072 + i0 + tx];
    __syncthreads();
    float* dst = (sel ? vt : kt) + (size_t)bh * (HSn * Tn);
#pragma unroll
    for (int r = 0; r < 32; r += 8)
        dst[(size_t)(i0 + ty + r) * Tn + t0 + tx] = tile[tx][ty + r];
}

// ---------------- Conv1d compression + LN(hs) + exact GELU ----------------
// input now transposed: base[i*1024 + t] (coalesced loads)
__global__ __launch_bounds__(256)
void conv_compress_kernel(const float* __restrict__ kt, const float* __restrict__ vt,
                          const float* __restrict__ conv_w,
                          const float* __restrict__ ln_comp_w,
                          float* __restrict__ kc, float* __restrict__ vc)
{
    __shared__ float shW[64 * 33];
    __shared__ float shIn[1104];
    __shared__ float sOut[63 * 65];

    const int bh  = blockIdx.x;
    const int sel = blockIdx.y;
    const float* base = (sel ? vt : kt) + (size_t)bh * (HSn * Tn);
    float* out = (sel ? vc : kc) + (size_t)bh * NBn * 64;

    const int tid = threadIdx.x;
    const int og = tid >> 4;
    const int ng = tid & 15;

    float acc[16];
#pragma unroll
    for (int i = 0; i < 16; ++i) acc[i] = 0.f;

    for (int i = 0; i < 64; ++i) {
        __syncthreads();
        for (int idx = tid; idx < 2048; idx += 256) {
            int o = idx >> 5, kk = idx & 31;
            shW[o * 33 + kk] = conv_w[((size_t)o * 64 + i) * 32 + kk];
        }
        const float* row = base + (size_t)i * Tn;
        for (int t = tid; t < 1024; t += 256)
            shIn[(t >> 4) * 17 + (t & 15)] = row[t];
        if (tid < 17) shIn[1087 + tid] = 0.f;
        __syncthreads();

#pragma unroll 4
        for (int kk = 0; kk < 32; ++kk) {
            const float w0 = shW[(og * 4 + 0) * 33 + kk];
            const float w1 = shW[(og * 4 + 1) * 33 + kk];
            const float w2 = shW[(og * 4 + 2) * 33 + kk];
            const float w3 = shW[(og * 4 + 3) * 33 + kk];
            const int hi = kk >> 4, lo = kk & 15;
#pragma unroll
            for (int q = 0; q < 4; ++q) {
                int nb = ng * 4 + q;
                float xin = shIn[(nb + hi) * 17 + lo];
                acc[0 + q]  = fmaf(w0, xin, acc[0 + q]);
                acc[4 + q]  = fmaf(w1, xin, acc[4 + q]);
                acc[8 + q]  = fmaf(w2, xin, acc[8 + q]);
                acc[12 + q] = fmaf(w3, xin, acc[12 + q]);
            }
        }
    }
    __syncthreads();
#pragma unroll
    for (int s = 0; s < 4; ++s)
#pragma unroll
        for (int q = 0; q < 4; ++q) {
            int nb = ng * 4 + q;
            if (nb < 63) sOut[nb * 65 + og * 4 + s] = acc[s * 4 + q];
        }
    __syncthreads();

    const int warp = tid >> 5, lane = tid & 31;
    for (int nb = warp; nb < 63; nb += 8) {
        float x0 = sOut[nb * 65 + lane];
        float x1 = sOut[nb * 65 + 32 + lane];
        float sm = x0 + x1, sq = x0 * x0 + x1 * x1;
#pragma unroll
        for (int off = 16; off; off >>= 1) {
            sm += __shfl_xor_sync(0xffffffffu, sm, off);
            sq += __shfl_xor_sync(0xffffffffu, sq, off);
        }
        float mean = sm * (1.f / 64.f);
        float var  = sq * (1.f / 64.f) - mean * mean;
        float inv  = rsqrtf(var + EPSf);
        float z0 = (x0 - mean) * inv * ln_comp_w[lane];
        float z1 = (x1 - mean) * inv * ln_comp_w[32 + lane];
        out[nb * 64 + lane]      = 0.5f * z0 * (1.f + erff(z0 * 0.70710678118654752f));
        out[nb * 64 + 32 + lane] = 0.5f * z1 * (1.f + erff(z1 * 0.70710678118654752f));
    }
}

// ---------------- Local banded causal attention ----------------
#define LOC_SMEM_FLOATS (64 * 193 + 192 * 64 + 8 * 192)
__global__ __launch_bounds__(256)
void local_attn_kernel(const float* __restrict__ qkv, float* __restrict__ outp)
{
    extern __shared__ float sm[];
    float* Kt    = sm;
    float* V     = sm + 64 * 193;
    float* probs = V + 192 * 64;

    const int qtile = blockIdx.x, bh = blockIdx.y;
    const int b = bh >> 4, h = bh & 15;
    const int qstart = qtile * 64;
    const int kstart = qstart - 128;
    const float* qbase = qkv + (size_t)b * Tn * 3072 + h * 64;

    for (int idx = threadIdx.x; idx < 192 * 64; idx += 256) {
        int j = idx >> 6, d = idx & 63;
        int t = kstart + j;
        float kv = 0.f, vv = 0.f;
        if (t >= 0) {
            const float* p = qbase + (size_t)t * 3072;
            kv = p[1024 + d];
            vv = p[2048 + d];
        }
        Kt[d * 193 + j] = kv;
        V[idx] = vv;
    }
    __syncthreads();

    const int warp = threadIdx.x >> 5, lane = threadIdx.x & 31;
    const int jlo_base = (kstart < 0) ? -kstart : 0;

    for (int r = 0; r < 8; ++r) {
        const int qi = warp * 8 + r;
        const int qg = qstart + qi;
        float qreg[64];
        const float* qp = qbase + (size_t)qg * 3072;
#pragma unroll
        for (int d = 0; d < 64; ++d) qreg[d] = __ldg(qp + d);

        const int jlo = (qi > jlo_base) ? qi : jlo_base;
        const int jhi = qi + 128;

        float mx = -1e30f;
        float sv[6];
#pragma unroll
        for (int m = 0; m < 6; ++m) {
            int j = lane + 32 * m;
            float s = -1e30f;
            if (32 * m <= jhi && 32 * m + 31 >= jlo && j >= jlo && j <= jhi) {
                float a = 0.f;
#pragma unroll
                for (int d = 0; d < 64; ++d) a = fmaf(qreg[d], Kt[d * 193 + j], a);
                s = a * 0.125f;
            }
            sv[m] = s;
            mx = fmaxf(mx, s);
        }
#pragma unroll
        for (int off = 16; off; off >>= 1) mx = fmaxf(mx, __shfl_xor_sync(0xffffffffu, mx, off));

        float sum = 0.f;
#pragma unroll
        for (int m = 0; m < 6; ++m) {
            int j = lane + 32 * m;
            float p = (sv[m] > -1e29f) ? __expf(sv[m] - mx) : 0.f;
            probs[warp * 192 + j] = p;
            sum += p;
        }
#pragma unroll
        for (int off = 16; off; off >>= 1) sum += __shfl_xor_sync(0xffffffffu, sum, off);
        const float invs = 1.f / sum;
        __syncwarp();

        float a0 = 0.f, a1 = 0.f;
        const int d0 = lane * 2;
        const float* pw = probs + warp * 192;
#pragma unroll 4
        for (int j = jlo; j <= jhi; ++j) {
            float p = pw[j];
            float2 v2 = *(const float2*)&V[j * 64 + d0];
            a0 = fmaf(p, v2.x, a0);
            a1 = fmaf(p, v2.y, a1);
        }
        float* op = outp + ((size_t)(b * Tn + qg)) * Cn + h * 64 + d0;
        op[0] = a0 * invs;
        op[1] = a1 * invs;
        __syncwarp();
    }
}

// ---------------- Compressed-KV attention ----------------
__global__ __launch_bounds__(256)
void comp_attn_kernel(const float* __restrict__ qkv, const float* __restrict__ kc,
                      const float* __restrict__ vc, float* __restrict__ outp)
{
    __shared__ float Kct[64 * 64];
    __shared__ float Vc[63 * 64];
    __shared__ float probs[8 * 64];

    const int bh = blockIdx.y;
    const int b = bh >> 4, h = bh & 15;
    const int qstart = blockIdx.x * 128;

    for (int idx = threadIdx.x; idx < 63 * 64; idx += 256) {
        int j = idx >> 6, d = idx & 63;
        Kct[d * 64 + j] = kc[(size_t)bh * 63 * 64 + idx];
        Vc[idx]         = vc[(size_t)bh * 63 * 64 + idx];
    }
    __syncthreads();

    const int warp = threadIdx.x >> 5, lane = threadIdx.x & 31;
    const float* qbase = qkv + (size_t)b * Tn * 3072 + h * 64;

    for (int r = 0; r < 16; ++r) {
        const int qg = qstart + warp * 16 + r;
        const int nk = (qg < 62 ? qg : 62) + 1;
        float qreg[64];
        const float* qp = qbase + (size_t)qg * 3072;
#pragma unroll
        for (int d = 0; d < 64; ++d) qreg[d] = __ldg(qp + d);

        float mx = -1e30f;
        float sv[2];
#pragma unroll
        for (int m = 0; m < 2; ++m) {
            int j = lane + 32 * m;
            float s = -1e30f;
            if (j < nk) {
                float a = 0.f;
#pragma unroll
                for (int d = 0; d < 64; ++d) a = fmaf(qreg[d], Kct[d * 64 + j], a);
                s = a * 0.125f;
            }
            sv[m] = s;
            mx = fmaxf(mx, s);
        }
#pragma unroll
        for (int off = 16; off; off >>= 1) mx = fmaxf(mx, __shfl_xor_sync(0xffffffffu, mx, off));
        float sum = 0.f;
#pragma unroll
        for (int m = 0; m < 2; ++m) {
            int j = lane + 32 * m;
            float p = (sv[m] > -1e29f) ? __expf(sv[m] - mx) : 0.f;
            probs[warp * 64 + j] = p;
            sum += p;
        }
#pragma unroll
        for (int off = 16; off; off >>= 1) sum += __shfl_xor_sync(0xffffffffu, sum, off);
        const float invs = 1.f / sum;
        __syncwarp();

        float a0 = 0.f, a1 = 0.f;
        const int d0 = lane * 2;
        const float* pw = probs + warp * 64;
        for (int j = 0; j < nk; ++j) {
            float p = pw[j];
            float2 v2 = *(const float2*)&Vc[j * 64 + d0];
            a0 = fmaf(p, v2.x, a0);
            a1 = fmaf(p, v2.y, a1);
        }
        float* op = outp + ((size_t)(b * Tn + qg)) * Cn + h * 64 + d0;
        op[0] = a0 * invs;
        op[1] = a1 * invs;
        __syncwarp();
    }
}

// ---------------- In-place row LayerNorm over C=1024 ----------------
__global__ __launch_bounds__(256)
void ln_rows_kernel(float* __restrict__ buf, const float* __restrict__ w)
{
    __shared__ float rs[8], rq[8], fin[2];
    const size_t row = blockIdx.x;
    float* p = buf + row * 1024;
    float x[4];
    float sm = 0.f, sq = 0.f;
#pragma unroll
    for (int k = 0; k < 4; ++k) {
        x[k] = p[threadIdx.x + k * 256];
        sm += x[k]; sq += x[k] * x[k];
    }
    const int warp = threadIdx.x >> 5, lane = threadIdx.x & 31;
#pragma unroll
    for (int off = 16; off; off >>= 1) {
        sm += __shfl_xor_sync(0xffffffffu, sm, off);
        sq += __shfl_xor_sync(0xffffffffu, sq, off);
    }
    if (lane == 0) { rs[warp] = sm; rq[warp] = sq; }
    __syncthreads();
    if (threadIdx.x == 0) {
        float a = 0.f, c = 0.f;
#pragma unroll
        for (int i = 0; i < 8; ++i) { a += rs[i]; c += rq[i]; }
        float mean = a * (1.f / 1024.f);
        float var  = c * (1.f / 1024.f) - mean * mean;
        fin[0] = mean;
        fin[1] = rsqrtf(var + EPSf);
    }
    __syncthreads();
    const float mean = fin[0], inv = fin[1];
#pragma unroll
    for (int k = 0; k < 4; ++k) {
        int c = threadIdx.x + k * 256;
        p[c] = (x[k] - mean) * inv * w[c];
    }
}

// ---------------- Gating MLP (one block per batch) ----------------
__global__ __launch_bounds__(256)
void gate_kernel(const float* __restrict__ localn, const float* __restrict__ comp,
                 const float* __restrict__ w1, const float* __restrict__ lnw,
                 const float* __restrict__ w2, float* __restrict__ gates)
{
    __shared__ float feats[2048];
    __shared__ float hsh[1024];
    __shared__ float rs[8], rq[8], fin[2];
    __shared__ float rl0[8], rl1[8];

    const int b = blockIdx.x;
    for (int idx = threadIdx.x; idx < 1024; idx += 256) {
        feats[idx]        = localn[((size_t)b * Tn + 1023) * Cn + idx];
        feats[1024 + idx] = comp  [((size_t)b * Tn + 1023) * Cn + idx];
    }
    __syncthreads();

#pragma unroll
    for (int jj = 0; jj < 4; ++jj) {
        int j = jj * 256 + threadIdx.x;
        const float4* wr = (const float4*)(w1 + (size_t)j * 2048);
        float a = 0.f;
        for (int c4 = 0; c4 < 512; ++c4) {
            float4 wv = __ldg(wr + c4);
            float4 fv = *(const float4*)&feats[c4 * 4];
            a += wv.x * fv.x + wv.y * fv.y + wv.z * fv.z + wv.w * fv.w;
        }
        hsh[j] = a;
    }
    __syncthreads();

    float sm = 0.f, sq = 0.f;
#pragma unroll
    for (int jj = 0; jj < 4; ++jj) {
        float v = hsh[jj * 256 + threadIdx.x];
        sm += v; sq += v * v;
    }
    const int warp = threadIdx.x >> 5, lane = threadIdx.x & 31;
#pragma unroll
    for (int off = 16; off; off >>= 1) {
        sm += __shfl_xor_sync(0xffffffffu, sm, off);
        sq += __shfl_xor_sync(0xffffffffu, sq, off);
    }
    if (lane == 0) { rs[warp] = sm; rq[warp] = sq; }
    __syncthreads();
    if (threadIdx.x == 0) {
        float a = 0.f, c = 0.f;
#pragma unroll
        for (int i = 0; i < 8; ++i) { a += rs[i]; c += rq[i]; }
        float mean = a * (1.f / 1024.f);
        float var  = c * (1.f / 1024.f) - mean * mean;
        fin[0] = mean;
        fin[1] = rsqrtf(var + EPSf);
    }
    __syncthreads();
    const float mean = fin[0], inv = fin[1];

    float l0 = 0.f, l1 = 0.f;
#pragma unroll
    for (int jj = 0; jj < 4; ++jj) {
        int j = jj * 256 + threadIdx.x;
        float hp = (hsh[j] - mean) * inv * lnw[j];
        hp = fmaxf(hp, 0.f);
        l0 = fmaf(hp, w2[j], l0);
        l1 = fmaf(hp, w2[1024 + j], l1);
    }
#pragma unroll
    for (int off = 16; off; off >>= 1) {
        l0 += __shfl_xor_sync(0xffffffffu, l0, off);
        l1 += __shfl_xor_sync(0xffffffffu, l1, off);
    }
    if (lane == 0) { rl0[warp] = l0; rl1[warp] = l1; }
    __syncthreads();
    if (threadIdx.x == 0) {
        float a = 0.f, c = 0.f;
#pragma unroll
        for (int i = 0; i < 8; ++i) { a += rl0[i]; c += rl1[i]; }
        float m = fmaxf(a, c);
        float e0 = __expf(a - m), e1 = __expf(c - m);
        float s = e0 + e1;
        gates[2 * b]     = e0 / s;
        gates[2 * b + 1] = e1 / s;
    }
}

// ---------------- Gated combination ----------------
__global__ __launch_bounds__(256)
void combine_kernel(const float* __restrict__ ln, const float* __restrict__ cp,
                    const float* __restrict__ gates, float* __restrict__ out)
{
    const int idx = blockIdx.x * 256 + threadIdx.x;
    const int b = idx >> 18;
    const float g0 = gates[2 * b], g1 = gates[2 * b + 1];
    float4 a = ((const float4*)ln)[idx];
    float4 c = ((const float4*)cp)[idx];
    ((float4*)out)[idx] = make_float4(g0 * a.x + g1 * c.x, g0 * a.y + g1 * c.y,
                                      g0 * a.z + g1 * c.z, g0 * a.w + g1 * c.w);
}

// ---------------- launch ----------------
extern "C" void kernel_launch(void* const* d_in, const int* in_sizes, int n_in,
                              void* d_out, int out_size)
{
    const float* x          = (const float*)d_in[0];
    const float* c_attn_w   = (const float*)d_in[1];
    const float* conv_w     = (const float*)d_in[2];
    const float* ln_comp_w  = (const float*)d_in[3];
    const float* ln_local_w = (const float*)d_in[4];
    const float* gate_w1    = (const float*)d_in[5];
    const float* gate_ln_w  = (const float*)d_in[6];
    const float* gate_w2    = (const float*)d_in[7];
    const float* c_proj_w   = (const float*)d_in[8];
    float* y = (float*)d_out;

    float *qkv, *kc, *vc, *loc, *cmp, *comb, *gates, *kt, *vt;
    __nv_bfloat16 *ah, *al, *bh, *bl;
    cudaGetSymbolAddress((void**)&qkv,   g_qkv);
    cudaGetSymbolAddress((void**)&kc,    g_kc);
    cudaGetSymbolAddress((void**)&vc,    g_vc);
    cudaGetSymbolAddress((void**)&loc,   g_loc);
    cudaGetSymbolAddress((void**)&cmp,   g_cmp);
    cudaGetSymbolAddress((void**)&comb,  g_comb);
    cudaGetSymbolAddress((void**)&gates, g_gates);
    cudaGetSymbolAddress((void**)&kt,    g_kt);
    cudaGetSymbolAddress((void**)&vt,    g_vt);
    cudaGetSymbolAddress((void**)&ah,    g_ah);
    cudaGetSymbolAddress((void**)&al,    g_al);
    cudaGetSymbolAddress((void**)&bh,    g_bh);
    cudaGetSymbolAddress((void**)&bl,    g_bl);

    cudaFuncSetAttribute(local_attn_kernel, cudaFuncAttributeMaxDynamicSharedMemorySize,
                         LOC_SMEM_FLOATS * (int)sizeof(float));
    cudaFuncSetAttribute(gemm_bf16_mma, cudaFuncAttributeMaxDynamicSharedMemorySize,
                         GEMM_SMEM_BYTES);

    const int nX  = Bn * Tn * Cn;       // 8M
    const int nW1 = 3 * Cn * Cn;        // 3M
    const int nW2 = Cn * Cn;            // 1M

    // 1) split inputs + c_attn weights to bf16 hi/lo
    split_bf16_kernel<<<(nX / 4 + 255) / 256, 256>>>((const float4*)x,
        (__nv_bfloat162*)ah, (__nv_bfloat162*)al, nX / 4);
    split_bf16_kernel<<<(nW1 / 4 + 255) / 256, 256>>>((const float4*)c_attn_w,
        (__nv_bfloat162*)bh, (__nv_bfloat162*)bl, nW1 / 4);
    // 2) QKV projection on tensor cores (mma.sync): [8192,3072]
    gemm_bf16_mma<<<dim3(3072 / 128, 8192 / 128), 256, GEMM_SMEM_BYTES>>>(
        ah, al, bh, bl, qkv, 3072, 1024);
    // 3) transpose K/V heads for coalesced conv input
    transpose_kv_kernel<<<dim3(Tn / 32, HSn / 32, Bn * Hn * 2), 256>>>(qkv, kt, vt);
    // 4) compression conv + LN + GELU for k and v
    conv_compress_kernel<<<dim3(Bn * Hn, 2), 256>>>(kt, vt, conv_w, ln_comp_w, kc, vc);
    // 5) local banded attention -> g_loc
    local_attn_kernel<<<dim3(Tn / 64, Bn * Hn), 256, LOC_SMEM_FLOATS * sizeof(float)>>>(qkv, loc);
    // 6) in-place LN over C on local output
    ln_rows_kernel<<<Bn * Tn, 256>>>(loc, ln_local_w);
    // 7) compressed attention -> g_cmp
    comp_attn_kernel<<<dim3(Tn / 128, Bn * Hn), 256>>>(qkv, kc, vc, cmp);
    // 8) gating from last-token features
    gate_kernel<<<Bn, 256>>>(loc, cmp, gate_w1, gate_ln_w, gate_w2, gates);
    // 9) gated combine
    combine_kernel<<<(Bn * Tn * Cn / 4) / 256, 256>>>(loc, cmp, gates, comb);
    // 10) split combined + c_proj weights, output projection on tensor cores
    split_bf16_kernel<<<(nX / 4 + 255) / 256, 256>>>((const float4*)comb,
        (__nv_bfloat162*)ah, (__nv_bfloat162*)al, nX / 4);
    split_bf16_kernel<<<(nW2 / 4 + 255) / 256, 256>>>((const float4*)c_proj_w,
        (__nv_bfloat162*)bh, (__nv_bfloat162*)bl, nW2 / 4);
    gemm_bf16_mma<<<dim3(1024 / 128, 8192 / 128), 256, GEMM_SMEM_BYTES>>>(
        ah, al, bh, bl, y, 1024, 1024);
}

// round 16
// speedup vs baseline: 1.0292x; 1.0292x over previous
#include <cuda_runtime.h>
#include <cuda_bf16.h>
#include <math.h>
#include <stdint.h>

// Problem constants
#define Bn   8
#define Tn   1024
#define Cn   1024
#define Hn   16
#define HSn  64
#define NBn  63
#define WINn 128
#define EPSf 1e-5f

// ---------------- scratch (device globals; no allocation) ----------------
__device__ float g_qkv [Bn * Tn * 3 * Cn];        // [B,T,3C]
__device__ float g_kc  [Bn * Hn * NBn * HSn];
__device__ float g_vc  [Bn * Hn * NBn * HSn];
__device__ float g_loc [Bn * Tn * Cn];
__device__ float g_cmp [Bn * Tn * Cn];
__device__ float g_comb[Bn * Tn * Cn];
__device__ float g_gates[Bn * 2];
__device__ float g_kt  [Bn * Hn * HSn * Tn];      // transposed K heads [bh][i][t]
__device__ float g_vt  [Bn * Hn * HSn * Tn];
// bf16 split buffers (reused between the two GEMMs)
__device__ __nv_bfloat16 g_ah[Bn * Tn * Cn];      // 8M
__device__ __nv_bfloat16 g_al[Bn * Tn * Cn];
__device__ __nv_bfloat16 g_bh[3 * Cn * Cn];       // 3M (covers both weight mats)
__device__ __nv_bfloat16 g_bl[3 * Cn * Cn];

// ================= helpers =================
__device__ __forceinline__ uint32_t smem_to_u32(const void* p) {
    uint32_t a;
    asm("{ .reg .u64 t; cvta.to.shared.u64 t, %1; cvt.u32.u64 %0, t; }" : "=r"(a) : "l"(p));
    return a;
}
__device__ __forceinline__ void cp16(uint32_t dst, const void* src) {
    asm volatile("cp.async.cg.shared.global [%0], [%1], 16;" :: "r"(dst), "l"(src) : "memory");
}
__device__ __forceinline__ void ldsm_x4(uint32_t& r0, uint32_t& r1, uint32_t& r2, uint32_t& r3,
                                        uint32_t addr) {
    asm volatile("ldmatrix.sync.aligned.m8n8.x4.shared.b16 {%0,%1,%2,%3}, [%4];"
                 : "=r"(r0), "=r"(r1), "=r"(r2), "=r"(r3) : "r"(addr));
}
__device__ __forceinline__ void mma_bf16(float* c, const uint32_t* a, const uint32_t* b) {
    asm volatile(
        "mma.sync.aligned.m16n8k16.row.col.f32.bf16.bf16.f32 "
        "{%0,%1,%2,%3}, {%4,%5,%6,%7}, {%8,%9}, {%0,%1,%2,%3};"
        : "+f"(c[0]), "+f"(c[1]), "+f"(c[2]), "+f"(c[3])
        : "r"(a[0]), "r"(a[1]), "r"(a[2]), "r"(a[3]), "r"(b[0]), "r"(b[1]));
}
// swizzled byte offset inside a [128 rows][32 bf16] tile (64B rows, 4x16B chunks)
__device__ __forceinline__ uint32_t swz(int row, int chunk) {
    return (uint32_t)(row * 64 + ((chunk ^ ((row >> 1) & 3)) << 4));
}

// ================= split fp32 -> (hi, lo) bf16 =================
__global__ __launch_bounds__(256)
void split_bf16_kernel(const float4* __restrict__ in, __nv_bfloat162* __restrict__ hi,
                       __nv_bfloat162* __restrict__ lo, int n4)
{
    int i = blockIdx.x * 256 + threadIdx.x;
    if (i >= n4) return;
    float4 v = in[i];
    __nv_bfloat16 h0 = __float2bfloat16(v.x), h1 = __float2bfloat16(v.y);
    __nv_bfloat16 h2 = __float2bfloat16(v.z), h3 = __float2bfloat16(v.w);
    __nv_bfloat16 l0 = __float2bfloat16(v.x - __bfloat162float(h0));
    __nv_bfloat16 l1 = __float2bfloat16(v.y - __bfloat162float(h1));
    __nv_bfloat16 l2 = __float2bfloat16(v.z - __bfloat162float(h2));
    __nv_bfloat16 l3 = __float2bfloat16(v.w - __bfloat162float(h3));
    hi[2 * i]     = __halves2bfloat162(h0, h1);
    hi[2 * i + 1] = __halves2bfloat162(h2, h3);
    lo[2 * i]     = __halves2bfloat162(l0, l1);
    lo[2 * i + 1] = __halves2bfloat162(l2, l3);
}

// ================= mma.sync bf16 GEMM (R14-proven BK=32 version) =================
// C[m,n] = sum_k A[m,k]*B[n,k], fp32 out, via Ah*Bh + Ah*Bl + Al*Bh.
// CTA tile 128x128, BK=32, 8 warps (2x4), warp tile 64x32, 2-stage cp.async.
__global__ __launch_bounds__(256, 2)
void gemm_bf16_mma(const __nv_bfloat16* __restrict__ Ah, const __nv_bfloat16* __restrict__ Al,
                   const __nv_bfloat16* __restrict__ Bh, const __nv_bfloat16* __restrict__ Bl,
                   float* __restrict__ C, int N, int K)
{
    __shared__ __align__(16) __nv_bfloat16 sA[2][128 * 32];
    __shared__ __align__(16) __nv_bfloat16 sB[2][128 * 32];

    const int tid = threadIdx.x;
    const int warp = tid >> 5, lane = tid & 31;
    const int wm = warp >> 2;       // 0..1 -> m offset wm*64
    const int wn = warp & 3;        // 0..3 -> n offset wn*32

    const int m0 = blockIdx.y * 128;
    const int n0 = blockIdx.x * 128;

    const __nv_bfloat16* Aps[3] = { Ah, Ah, Al };
    const __nv_bfloat16* Bps[3] = { Bh, Bl, Bh };

    const int sp = K >> 5;               // slabs per pass
    const int total_slabs = 3 * sp;

    const uint32_t aBase[2] = { smem_to_u32(&sA[0][0]), smem_to_u32(&sA[1][0]) };
    const uint32_t bBase[2] = { smem_to_u32(&sB[0][0]), smem_to_u32(&sB[1][0]) };

    // loader: thread t handles row t>>1, two 16B chunks {2*(t&1), 2*(t&1)+1}
    const int lrow = tid >> 1;
    const int lch0 = (tid & 1) << 1;

    auto load_slab = [&](int stage, int slab) {
        const int pass = slab / sp;
        const int k0 = (slab - pass * sp) << 5;
        const __nv_bfloat16* Ap = Aps[pass] + (size_t)(m0 + lrow) * K + k0;
        const __nv_bfloat16* Bp = Bps[pass] + (size_t)(n0 + lrow) * K + k0;
#pragma unroll
        for (int c = 0; c < 2; ++c) {
            const int ch = lch0 + c;
            cp16(aBase[stage] + swz(lrow, ch), Ap + ch * 8);
            cp16(bBase[stage] + swz(lrow, ch), Bp + ch * 8);
        }
        asm volatile("cp.async.commit_group;" ::: "memory");
    };

    float acc[4][4][4];
#pragma unroll
    for (int i = 0; i < 4; ++i)
#pragma unroll
        for (int j = 0; j < 4; ++j)
#pragma unroll
            for (int q = 0; q < 4; ++q) acc[i][j][q] = 0.f;

    load_slab(0, 0);
    load_slab(1, 1);

    const int l16 = lane & 15, lhi = lane >> 4;      // A ldmatrix addressing
    const int l8 = lane & 7, grp = lane >> 3;        // B ldmatrix addressing

    for (int s = 0; s < total_slabs; ++s) {
        if (s == total_slabs - 1) asm volatile("cp.async.wait_group 0;" ::: "memory");
        else                      asm volatile("cp.async.wait_group 1;" ::: "memory");
        __syncthreads();

        const int st = s & 1;
        const uint32_t aB = aBase[st], bB = bBase[st];
#pragma unroll
        for (int j = 0; j < 2; ++j) {                 // two k16 steps per slab
            uint32_t af[4][4];
#pragma unroll
            for (int mt = 0; mt < 4; ++mt) {
                const int row = wm * 64 + mt * 16 + l16;
                ldsm_x4(af[mt][0], af[mt][1], af[mt][2], af[mt][3],
                        aB + swz(row, 2 * j + lhi));
            }
            uint32_t bfr[4][2];
#pragma unroll
            for (int g = 0; g < 2; ++g) {
                const int row = wn * 32 + g * 16 + ((grp >> 1) << 3) + l8;
                uint32_t r0, r1, r2, r3;
                ldsm_x4(r0, r1, r2, r3, bB + swz(row, 2 * j + (grp & 1)));
                bfr[g * 2 + 0][0] = r0; bfr[g * 2 + 0][1] = r1;
                bfr[g * 2 + 1][0] = r2; bfr[g * 2 + 1][1] = r3;
            }
#pragma unroll
            for (int mt = 0; mt < 4; ++mt)
#pragma unroll
                for (int nt = 0; nt < 4; ++nt)
                    mma_bf16(acc[mt][nt], af[mt], bfr[nt]);
        }
        __syncthreads();
        if (s + 2 < total_slabs) load_slab(st, s + 2);
    }

    // epilogue
    const int gr = lane >> 2, gc = (lane & 3) << 1;
#pragma unroll
    for (int mt = 0; mt < 4; ++mt) {
#pragma unroll
        for (int nt = 0; nt < 4; ++nt) {
            float* p0 = C + (size_t)(m0 + wm * 64 + mt * 16 + gr) * N
                         + n0 + wn * 32 + nt * 8 + gc;
            float* p1 = p0 + (size_t)8 * N;
            *(float2*)p0 = make_float2(acc[mt][nt][0], acc[mt][nt][1]);
            *(float2*)p1 = make_float2(acc[mt][nt][2], acc[mt][nt][3]);
        }
    }
}

// ---------------- transpose K/V heads: qkv -> [bh][i][t] ----------------
__global__ __launch_bounds__(256)
void transpose_kv_kernel(const float* __restrict__ qkv,
                         float* __restrict__ kt, float* __restrict__ vt)
{
    __shared__ float tile[32][33];
    const int z = blockIdx.z;
    const int sel = z & 1, bh = z >> 1;
    const int b = bh >> 4, h = bh & 15;
    const float* src = qkv + (size_t)b * Tn * 3072 + 1024 + sel * 1024 + h * 64;
    const int t0 = blockIdx.x * 32, i0 = blockIdx.y * 32;
    const int tx = threadIdx.x & 31, ty = threadIdx.x >> 5;   // 32 x 8

#pragma unroll
    for (int r = 0; r < 32; r += 8)
        tile[ty + r][tx] = src[(size_t)(t0 + ty + r) * 3072 + i0 + tx];
    __syncthreads();
    float* dst = (sel ? vt : kt) + (size_t)bh * (HSn * Tn);
#pragma unroll
    for (int r = 0; r < 32; r += 8)
        dst[(size_t)(i0 + ty + r) * Tn + t0 + tx] = tile[tx][ty + r];
}

// ---------------- Conv1d compression + LN(hs) + exact GELU ----------------
// input transposed: base[i*1024 + t] (coalesced loads)
__global__ __launch_bounds__(256)
void conv_compress_kernel(const float* __restrict__ kt, const float* __restrict__ vt,
                          const float* __restrict__ conv_w,
                          const float* __restrict__ ln_comp_w,
                          float* __restrict__ kc, float* __restrict__ vc)
{
    __shared__ float shW[64 * 33];
    __shared__ float shIn[1104];
    __shared__ float sOut[63 * 65];

    const int bh  = blockIdx.x;
    const int sel = blockIdx.y;
    const float* base = (sel ? vt : kt) + (size_t)bh * (HSn * Tn);
    float* out = (sel ? vc : kc) + (size_t)bh * NBn * 64;

    const int tid = threadIdx.x;
    const int og = tid >> 4;
    const int ng = tid & 15;

    float acc[16];
#pragma unroll
    for (int i = 0; i < 16; ++i) acc[i] = 0.f;

    for (int i = 0; i < 64; ++i) {
        __syncthreads();
        for (int idx = tid; idx < 2048; idx += 256) {
            int o = idx >> 5, kk = idx & 31;
            shW[o * 33 + kk] = conv_w[((size_t)o * 64 + i) * 32 + kk];
        }
        const float* row = base + (size_t)i * Tn;
        for (int t = tid; t < 1024; t += 256)
            shIn[(t >> 4) * 17 + (t & 15)] = row[t];
        if (tid < 17) shIn[1087 + tid] = 0.f;
        __syncthreads();

#pragma unroll 4
        for (int kk = 0; kk < 32; ++kk) {
            const float w0 = shW[(og * 4 + 0) * 33 + kk];
            const float w1 = shW[(og * 4 + 1) * 33 + kk];
            const float w2 = shW[(og * 4 + 2) * 33 + kk];
            const float w3 = shW[(og * 4 + 3) * 33 + kk];
            const int hi = kk >> 4, lo = kk & 15;
#pragma unroll
            for (int q = 0; q < 4; ++q) {
                int nb = ng * 4 + q;
                float xin = shIn[(nb + hi) * 17 + lo];
                acc[0 + q]  = fmaf(w0, xin, acc[0 + q]);
                acc[4 + q]  = fmaf(w1, xin, acc[4 + q]);
                acc[8 + q]  = fmaf(w2, xin, acc[8 + q]);
                acc[12 + q] = fmaf(w3, xin, acc[12 + q]);
            }
        }
    }
    __syncthreads();
#pragma unroll
    for (int s = 0; s < 4; ++s)
#pragma unroll
        for (int q = 0; q < 4; ++q) {
            int nb = ng * 4 + q;
            if (nb < 63) sOut[nb * 65 + og * 4 + s] = acc[s * 4 + q];
        }
    __syncthreads();

    const int warp = tid >> 5, lane = tid & 31;
    for (int nb = warp; nb < 63; nb += 8) {
        float x0 = sOut[nb * 65 + lane];
        float x1 = sOut[nb * 65 + 32 + lane];
        float sm = x0 + x1, sq = x0 * x0 + x1 * x1;
#pragma unroll
        for (int off = 16; off; off >>= 1) {
            sm += __shfl_xor_sync(0xffffffffu, sm, off);
            sq += __shfl_xor_sync(0xffffffffu, sq, off);
        }
        float mean = sm * (1.f / 64.f);
        float var  = sq * (1.f / 64.f) - mean * mean;
        float inv  = rsqrtf(var + EPSf);
        float z0 = (x0 - mean) * inv * ln_comp_w[lane];
        float z1 = (x1 - mean) * inv * ln_comp_w[32 + lane];
        out[nb * 64 + lane]      = 0.5f * z0 * (1.f + erff(z0 * 0.70710678118654752f));
        out[nb * 64 + 32 + lane] = 0.5f * z1 * (1.f + erff(z1 * 0.70710678118654752f));
    }
}

// ---------------- Local banded causal attention ----------------
#define LOC_SMEM_FLOATS (64 * 193 + 192 * 64 + 8 * 192)
__global__ __launch_bounds__(256)
void local_attn_kernel(const float* __restrict__ qkv, float* __restrict__ outp)
{
    extern __shared__ float sm[];
    float* Kt    = sm;
    float* V     = sm + 64 * 193;
    float* probs = V + 192 * 64;

    const int qtile = blockIdx.x, bh = blockIdx.y;
    const int b = bh >> 4, h = bh & 15;
    const int qstart = qtile * 64;
    const int kstart = qstart - 128;
    const float* qbase = qkv + (size_t)b * Tn * 3072 + h * 64;

    for (int idx = threadIdx.x; idx < 192 * 64; idx += 256) {
        int j = idx >> 6, d = idx & 63;
        int t = kstart + j;
        float kv = 0.f, vv = 0.f;
        if (t >= 0) {
            const float* p = qbase + (size_t)t * 3072;
            kv = p[1024 + d];
            vv = p[2048 + d];
        }
        Kt[d * 193 + j] = kv;
        V[idx] = vv;
    }
    __syncthreads();

    const int warp = threadIdx.x >> 5, lane = threadIdx.x & 31;
    const int jlo_base = (kstart < 0) ? -kstart : 0;

    for (int r = 0; r < 8; ++r) {
        const int qi = warp * 8 + r;
        const int qg = qstart + qi;
        float qreg[64];
        const float* qp = qbase + (size_t)qg * 3072;
#pragma unroll
        for (int d = 0; d < 64; ++d) qreg[d] = __ldg(qp + d);

        const int jlo = (qi > jlo_base) ? qi : jlo_base;
        const int jhi = qi + 128;

        float mx = -1e30f;
        float sv[6];
#pragma unroll
        for (int m = 0; m < 6; ++m) {
            int j = lane + 32 * m;
            float s = -1e30f;
            if (32 * m <= jhi && 32 * m + 31 >= jlo && j >= jlo && j <= jhi) {
                float a = 0.f;
#pragma unroll
                for (int d = 0; d < 64; ++d) a = fmaf(qreg[d], Kt[d * 193 + j], a);
                s = a * 0.125f;
            }
            sv[m] = s;
            mx = fmaxf(mx, s);
        }
#pragma unroll
        for (int off = 16; off; off >>= 1) mx = fmaxf(mx, __shfl_xor_sync(0xffffffffu, mx, off));

        float sum = 0.f;
#pragma unroll
        for (int m = 0; m < 6; ++m) {
            int j = lane + 32 * m;
            float p = (sv[m] > -1e29f) ? __expf(sv[m] - mx) : 0.f;
            probs[warp * 192 + j] = p;
            sum += p;
        }
#pragma unroll
        for (int off = 16; off; off >>= 1) sum += __shfl_xor_sync(0xffffffffu, sum, off);
        const float invs = 1.f / sum;
        __syncwarp();

        float a0 = 0.f, a1 = 0.f;
        const int d0 = lane * 2;
        const float* pw = probs + warp * 192;
#pragma unroll 4
        for (int j = jlo; j <= jhi; ++j) {
            float p = pw[j];
            float2 v2 = *(const float2*)&V[j * 64 + d0];
            a0 = fmaf(p, v2.x, a0);
            a1 = fmaf(p, v2.y, a1);
        }
        float* op = outp + ((size_t)(b * Tn + qg)) * Cn + h * 64 + d0;
        op[0] = a0 * invs;
        op[1] = a1 * invs;
        __syncwarp();
    }
}

// ---------------- Compressed-KV attention ----------------
__global__ __launch_bounds__(256)
void comp_attn_kernel(const float* __restrict__ qkv, const float* __restrict__ kc,
                      const float* __restrict__ vc, float* __restrict__ outp)
{
    __shared__ float Kct[64 * 64];
    __shared__ float Vc[63 * 64];
    __shared__ float probs[8 * 64];

    const int bh = blockIdx.y;
    const int b = bh >> 4, h = bh & 15;
    const int qstart = blockIdx.x * 128;

    for (int idx = threadIdx.x; idx < 63 * 64; idx += 256) {
        int j = idx >> 6, d = idx & 63;
        Kct[d * 64 + j] = kc[(size_t)bh * 63 * 64 + idx];
        Vc[idx]         = vc[(size_t)bh * 63 * 64 + idx];
    }
    __syncthreads();

    const int warp = threadIdx.x >> 5, lane = threadIdx.x & 31;
    const float* qbase = qkv + (size_t)b * Tn * 3072 + h * 64;

    for (int r = 0; r < 16; ++r) {
        const int qg = qstart + warp * 16 + r;
        const int nk = (qg < 62 ? qg : 62) + 1;
        float qreg[64];
        const float* qp = qbase + (size_t)qg * 3072;
#pragma unroll
        for (int d = 0; d < 64; ++d) qreg[d] = __ldg(qp + d);

        float mx = -1e30f;
        float sv[2];
#pragma unroll
        for (int m = 0; m < 2; ++m) {
            int j = lane + 32 * m;
            float s = -1e30f;
            if (j < nk) {
                float a = 0.f;
#pragma unroll
                for (int d = 0; d < 64; ++d) a = fmaf(qreg[d], Kct[d * 64 + j], a);
                s = a * 0.125f;
            }
            sv[m] = s;
            mx = fmaxf(mx, s);
        }
#pragma unroll
        for (int off = 16; off; off >>= 1) mx = fmaxf(mx, __shfl_xor_sync(0xffffffffu, mx, off));
        float sum = 0.f;
#pragma unroll
        for (int m = 0; m < 2; ++m) {
            int j = lane + 32 * m;
            float p = (sv[m] > -1e29f) ? __expf(sv[m] - mx) : 0.f;
            probs[warp * 64 + j] = p;
            sum += p;
        }
#pragma unroll
        for (int off = 16; off; off >>= 1) sum += __shfl_xor_sync(0xffffffffu, sum, off);
        const float invs = 1.f / sum;
        __syncwarp();

        float a0 = 0.f, a1 = 0.f;
        const int d0 = lane * 2;
        const float* pw = probs + warp * 64;
        for (int j = 0; j < nk; ++j) {
            float p = pw[j];
            float2 v2 = *(const float2*)&Vc[j * 64 + d0];
            a0 = fmaf(p, v2.x, a0);
            a1 = fmaf(p, v2.y, a1);
        }
        float* op = outp + ((size_t)(b * Tn + qg)) * Cn + h * 64 + d0;
        op[0] = a0 * invs;
        op[1] = a1 * invs;
        __syncwarp();
    }
}

// ---------------- In-place row LayerNorm over C=1024 ----------------
__global__ __launch_bounds__(256)
void ln_rows_kernel(float* __restrict__ buf, const float* __restrict__ w)
{
    __shared__ float rs[8], rq[8], fin[2];
    const size_t row = blockIdx.x;
    float* p = buf + row * 1024;
    float x[4];
    float sm = 0.f, sq = 0.f;
#pragma unroll
    for (int k = 0; k < 4; ++k) {
        x[k] = p[threadIdx.x + k * 256];
        sm += x[k]; sq += x[k] * x[k];
    }
    const int warp = threadIdx.x >> 5, lane = threadIdx.x & 31;
#pragma unroll
    for (int off = 16; off; off >>= 1) {
        sm += __shfl_xor_sync(0xffffffffu, sm, off);
        sq += __shfl_xor_sync(0xffffffffu, sq, off);
    }
    if (lane == 0) { rs[warp] = sm; rq[warp] = sq; }
    __syncthreads();
    if (threadIdx.x == 0) {
        float a = 0.f, c = 0.f;
#pragma unroll
        for (int i = 0; i < 8; ++i) { a += rs[i]; c += rq[i]; }
        float mean = a * (1.f / 1024.f);
        float var  = c * (1.f / 1024.f) - mean * mean;
        fin[0] = mean;
        fin[1] = rsqrtf(var + EPSf);
    }
    __syncthreads();
    const float mean = fin[0], inv = fin[1];
#pragma unroll
    for (int k = 0; k < 4; ++k) {
        int c = threadIdx.x + k * 256;
        p[c] = (x[k] - mean) * inv * w[c];
    }
}

// ---------------- Gating MLP (one block per batch) ----------------
__global__ __launch_bounds__(256)
void gate_kernel(const float* __restrict__ localn, const float* __restrict__ comp,
                 const float* __restrict__ w1, const float* __restrict__ lnw,
                 const float* __restrict__ w2, float* __restrict__ gates)
{
    __shared__ float feats[2048];
    __shared__ float hsh[1024];
    __shared__ float rs[8], rq[8], fin[2];
    __shared__ float rl0[8], rl1[8];

    const int b = blockIdx.x;
    for (int idx = threadIdx.x; idx < 1024; idx += 256) {
        feats[idx]        = localn[((size_t)b * Tn + 1023) * Cn + idx];
        feats[1024 + idx] = comp  [((size_t)b * Tn + 1023) * Cn + idx];
    }
    __syncthreads();

#pragma unroll
    for (int jj = 0; jj < 4; ++jj) {
        int j = jj * 256 + threadIdx.x;
        const float4* wr = (const float4*)(w1 + (size_t)j * 2048);
        float a = 0.f;
        for (int c4 = 0; c4 < 512; ++c4) {
            float4 wv = __ldg(wr + c4);
            float4 fv = *(const float4*)&feats[c4 * 4];
            a += wv.x * fv.x + wv.y * fv.y + wv.z * fv.z + wv.w * fv.w;
        }
        hsh[j] = a;
    }
    __syncthreads();

    float sm = 0.f, sq = 0.f;
#pragma unroll
    for (int jj = 0; jj < 4; ++jj) {
        float v = hsh[jj * 256 + threadIdx.x];
        sm += v; sq += v * v;
    }
    const int warp = threadIdx.x >> 5, lane = threadIdx.x & 31;
#pragma unroll
    for (int off = 16; off; off >>= 1) {
        sm += __shfl_xor_sync(0xffffffffu, sm, off);
        sq += __shfl_xor_sync(0xffffffffu, sq, off);
    }
    if (lane == 0) { rs[warp] = sm; rq[warp] = sq; }
    __syncthreads();
    if (threadIdx.x == 0) {
        float a = 0.f, c = 0.f;
#pragma unroll
        for (int i = 0; i < 8; ++i) { a += rs[i]; c += rq[i]; }
        float mean = a * (1.f / 1024.f);
        float var  = c * (1.f / 1024.f) - mean * mean;
        fin[0] = mean;
        fin[1] = rsqrtf(var + EPSf);
    }
    __syncthreads();
    const float mean = fin[0], inv = fin[1];

    float l0 = 0.f, l1 = 0.f;
#pragma unroll
    for (int jj = 0; jj < 4; ++jj) {
        int j = jj * 256 + threadIdx.x;
        float hp = (hsh[j] - mean) * inv * lnw[j];
        hp = fmaxf(hp, 0.f);
        l0 = fmaf(hp, w2[j], l0);
        l1 = fmaf(hp, w2[1024 + j], l1);
    }
#pragma unroll
    for (int off = 16; off; off >>= 1) {
        l0 += __shfl_xor_sync(0xffffffffu, l0, off);
        l1 += __shfl_xor_sync(0xffffffffu, l1, off);
    }
    if (lane == 0) { rl0[warp] = l0; rl1[warp] = l1; }
    __syncthreads();
    if (threadIdx.x == 0) {
        float a = 0.f, c = 0.f;
#pragma unroll
        for (int i = 0; i < 8; ++i) { a += rl0[i]; c += rl1[i]; }
        float m = fmaxf(a, c);
        float e0 = __expf(a - m), e1 = __expf(c - m);
        float s = e0 + e1;
        gates[2 * b]     = e0 / s;
        gates[2 * b + 1] = e1 / s;
    }
}

// ---------------- Gated combination ----------------
__global__ __launch_bounds__(256)
void combine_kernel(const float* __restrict__ ln, const float* __restrict__ cp,
                    const float* __restrict__ gates, float* __restrict__ out)
{
    const int idx = blockIdx.x * 256 + threadIdx.x;
    const int b = idx >> 18;
    const float g0 = gates[2 * b], g1 = gates[2 * b + 1];
    float4 a = ((const float4*)ln)[idx];
    float4 c = ((const float4*)cp)[idx];
    ((float4*)out)[idx] = make_float4(g0 * a.x + g1 * c.x, g0 * a.y + g1 * c.y,
                                      g0 * a.z + g1 * c.z, g0 * a.w + g1 * c.w);
}

// ---------------- launch ----------------
extern "C" void kernel_launch(void* const* d_in, const int* in_sizes, int n_in,
                              void* d_out, int out_size)
{
    const float* x          = (const float*)d_in[0];
    const float* c_attn_w   = (const float*)d_in[1];
    const float* conv_w     = (const float*)d_in[2];
    const float* ln_comp_w  = (const float*)d_in[3];
    const float* ln_local_w = (const float*)d_in[4];
    const float* gate_w1    = (const float*)d_in[5];
    const float* gate_ln_w  = (const float*)d_in[6];
    const float* gate_w2    = (const float*)d_in[7];
    const float* c_proj_w   = (const float*)d_in[8];
    float* y = (float*)d_out;

    float *qkv, *kc, *vc, *loc, *cmp, *comb, *gates, *kt, *vt;
    __nv_bfloat16 *ah, *al, *bh, *bl;
    cudaGetSymbolAddress((void**)&qkv,   g_qkv);
    cudaGetSymbolAddress((void**)&kc,    g_kc);
    cudaGetSymbolAddress((void**)&vc,    g_vc);
    cudaGetSymbolAddress((void**)&loc,   g_loc);
    cudaGetSymbolAddress((void**)&cmp,   g_cmp);
    cudaGetSymbolAddress((void**)&comb,  g_comb);
    cudaGetSymbolAddress((void**)&gates, g_gates);
    cudaGetSymbolAddress((void**)&kt,    g_kt);
    cudaGetSymbolAddress((void**)&vt,    g_vt);
    cudaGetSymbolAddress((void**)&ah,    g_ah);
    cudaGetSymbolAddress((void**)&al,    g_al);
    cudaGetSymbolAddress((void**)&bh,    g_bh);
    cudaGetSymbolAddress((void**)&bl,    g_bl);

    cudaFuncSetAttribute(local_attn_kernel, cudaFuncAttributeMaxDynamicSharedMemorySize,
                         LOC_SMEM_FLOATS * (int)sizeof(float));

    const int nX  = Bn * Tn * Cn;       // 8M
    const int nW1 = 3 * Cn * Cn;        // 3M
    const int nW2 = Cn * Cn;            // 1M

    // 1) split inputs + c_attn weights to bf16 hi/lo
    split_bf16_kernel<<<(nX / 4 + 255) / 256, 256>>>((const float4*)x,
        (__nv_bfloat162*)ah, (__nv_bfloat162*)al, nX / 4);
    split_bf16_kernel<<<(nW1 / 4 + 255) / 256, 256>>>((const float4*)c_attn_w,
        (__nv_bfloat162*)bh, (__nv_bfloat162*)bl, nW1 / 4);
    // 2) QKV projection on tensor cores (mma.sync): [8192,3072]
    gemm_bf16_mma<<<dim3(3072 / 128, 8192 / 128), 256>>>(ah, al, bh, bl, qkv, 3072, 1024);
    // 3) transpose K/V heads for coalesced conv input
    transpose_kv_kernel<<<dim3(Tn / 32, HSn / 32, Bn * Hn * 2), 256>>>(qkv, kt, vt);
    // 4) compression conv + LN + GELU for k and v
    conv_compress_kernel<<<dim3(Bn * Hn, 2), 256>>>(kt, vt, conv_w, ln_comp_w, kc, vc);
    // 5) local banded attention -> g_loc
    local_attn_kernel<<<dim3(Tn / 64, Bn * Hn), 256, LOC_SMEM_FLOATS * sizeof(float)>>>(qkv, loc);
    // 6) in-place LN over C on local output
    ln_rows_kernel<<<Bn * Tn, 256>>>(loc, ln_local_w);
    // 7) compressed attention -> g_cmp
    comp_attn_kernel<<<dim3(Tn / 128, Bn * Hn), 256>>>(qkv, kc, vc, cmp);
    // 8) gating from last-token features
    gate_kernel<<<Bn, 256>>>(loc, cmp, gate_w1, gate_ln_w, gate_w2, gates);
    // 9) gated combine
    combine_kernel<<<(Bn * Tn * Cn / 4) / 256, 256>>>(loc, cmp, gates, comb);
    // 10) split combined + c_proj weights, output projection on tensor cores
    split_bf16_kernel<<<(nX / 4 + 255) / 256, 256>>>((const float4*)comb,
        (__nv_bfloat162*)ah, (__nv_bfloat162*)al, nX / 4);
    split_bf16_kernel<<<(nW2 / 4 + 255) / 256, 256>>>((const float4*)c_proj_w,
        (__nv_bfloat162*)bh, (__nv_bfloat162*)bl, nW2 / 4);
    gemm_bf16_mma<<<dim3(1024 / 128, 8192 / 128), 256>>>(ah, al, bh, bl, y, 1024, 1024);
}

// round 17
// speedup vs baseline: 1.1394x; 1.1071x over previous
#include <cuda_runtime.h>
#include <cuda_bf16.h>
#include <math.h>
#include <stdint.h>

// Problem constants
#define Bn   8
#define Tn   1024
#define Cn   1024
#define Hn   16
#define HSn  64
#define NBn  63
#define WINn 128
#define EPSf 1e-5f

// ---------------- scratch (device globals; no allocation) ----------------
__device__ float g_qkv [Bn * Tn * 3 * Cn];        // [B,T,3C]
__device__ float g_kc  [Bn * Hn * NBn * HSn];
__device__ float g_vc  [Bn * Hn * NBn * HSn];
__device__ float g_loc [Bn * Tn * Cn];
__device__ float g_cmp [Bn * Tn * Cn];
__device__ float g_comb[Bn * Tn * Cn];
__device__ float g_gates[Bn * 2];
__device__ float g_kt  [Bn * Hn * HSn * Tn];      // transposed K heads [bh][i][t]
__device__ float g_vt  [Bn * Hn * HSn * Tn];
__device__ float g_convp[256 * 4 * NBn * 64];     // conv partials [bh*2+sel][ic][nb][o]
// bf16 split buffers (reused between the two GEMMs)
__device__ __nv_bfloat16 g_ah[Bn * Tn * Cn];      // 8M
__device__ __nv_bfloat16 g_al[Bn * Tn * Cn];
__device__ __nv_bfloat16 g_bh[3 * Cn * Cn];       // 3M (covers both weight mats)
__device__ __nv_bfloat16 g_bl[3 * Cn * Cn];

// ================= helpers =================
__device__ __forceinline__ uint32_t smem_to_u32(const void* p) {
    uint32_t a;
    asm("{ .reg .u64 t; cvta.to.shared.u64 t, %1; cvt.u32.u64 %0, t; }" : "=r"(a) : "l"(p));
    return a;
}
__device__ __forceinline__ void cp16(uint32_t dst, const void* src) {
    asm volatile("cp.async.cg.shared.global [%0], [%1], 16;" :: "r"(dst), "l"(src) : "memory");
}
__device__ __forceinline__ void ldsm_x4(uint32_t& r0, uint32_t& r1, uint32_t& r2, uint32_t& r3,
                                        uint32_t addr) {
    asm volatile("ldmatrix.sync.aligned.m8n8.x4.shared.b16 {%0,%1,%2,%3}, [%4];"
                 : "=r"(r0), "=r"(r1), "=r"(r2), "=r"(r3) : "r"(addr));
}
__device__ __forceinline__ void mma_bf16(float* c, const uint32_t* a, const uint32_t* b) {
    asm volatile(
        "mma.sync.aligned.m16n8k16.row.col.f32.bf16.bf16.f32 "
        "{%0,%1,%2,%3}, {%4,%5,%6,%7}, {%8,%9}, {%0,%1,%2,%3};"
        : "+f"(c[0]), "+f"(c[1]), "+f"(c[2]), "+f"(c[3])
        : "r"(a[0]), "r"(a[1]), "r"(a[2]), "r"(a[3]), "r"(b[0]), "r"(b[1]));
}
// swizzled byte offset inside a [128 rows][32 bf16] tile (64B rows, 4x16B chunks)
__device__ __forceinline__ uint32_t swz(int row, int chunk) {
    return (uint32_t)(row * 64 + ((chunk ^ ((row >> 1) & 3)) << 4));
}

// ================= split fp32 -> (hi, lo) bf16 =================
__global__ __launch_bounds__(256)
void split_bf16_kernel(const float4* __restrict__ in, __nv_bfloat162* __restrict__ hi,
                       __nv_bfloat162* __restrict__ lo, int n4)
{
    int i = blockIdx.x * 256 + threadIdx.x;
    if (i >= n4) return;
    float4 v = in[i];
    __nv_bfloat16 h0 = __float2bfloat16(v.x), h1 = __float2bfloat16(v.y);
    __nv_bfloat16 h2 = __float2bfloat16(v.z), h3 = __float2bfloat16(v.w);
    __nv_bfloat16 l0 = __float2bfloat16(v.x - __bfloat162float(h0));
    __nv_bfloat16 l1 = __float2bfloat16(v.y - __bfloat162float(h1));
    __nv_bfloat16 l2 = __float2bfloat16(v.z - __bfloat162float(h2));
    __nv_bfloat16 l3 = __float2bfloat16(v.w - __bfloat162float(h3));
    hi[2 * i]     = __halves2bfloat162(h0, h1);
    hi[2 * i + 1] = __halves2bfloat162(h2, h3);
    lo[2 * i]     = __halves2bfloat162(l0, l1);
    lo[2 * i + 1] = __halves2bfloat162(l2, l3);
}

// ================= mma.sync bf16 GEMM, BK=32, 3-stage cp.async =================
// C[m,n] = sum_k A[m,k]*B[n,k], fp32 out, via Ah*Bh + Ah*Bl + Al*Bh.
// CTA tile 128x128, 8 warps (2x4), warp tile 64x32.
// dynamic smem: 3 stages x (8KB A + 8KB B) = 48 KB.
#define GEMM_SMEM_BYTES 49152
__global__ __launch_bounds__(256, 2)
void gemm_bf16_mma(const __nv_bfloat16* __restrict__ Ah, const __nv_bfloat16* __restrict__ Al,
                   const __nv_bfloat16* __restrict__ Bh, const __nv_bfloat16* __restrict__ Bl,
                   float* __restrict__ C, int N, int K)
{
    extern __shared__ __align__(16) char dsm[];

    const int tid = threadIdx.x;
    const int warp = tid >> 5, lane = tid & 31;
    const int wm = warp >> 2;       // 0..1 -> m offset wm*64
    const int wn = warp & 3;        // 0..3 -> n offset wn*32

    const int m0 = blockIdx.y * 128;
    const int n0 = blockIdx.x * 128;

    const __nv_bfloat16* Aps[3] = { Ah, Ah, Al };
    const __nv_bfloat16* Bps[3] = { Bh, Bl, Bh };

    const int sp = K >> 5;               // slabs per pass
    const int total_slabs = 3 * sp;

    const uint32_t sbase = smem_to_u32(dsm);
    // stage st: A at st*16384, B at st*16384 + 8192

    const int lrow = tid >> 1;
    const int lch0 = (tid & 1) << 1;

    auto load_slab = [&](int stage, int slab) {
        const int pass = slab / sp;
        const int k0 = (slab - pass * sp) << 5;
        const __nv_bfloat16* Ap = Aps[pass] + (size_t)(m0 + lrow) * K + k0;
        const __nv_bfloat16* Bp = Bps[pass] + (size_t)(n0 + lrow) * K + k0;
        const uint32_t aB = sbase + stage * 16384;
        const uint32_t bB = aB + 8192;
#pragma unroll
        for (int c = 0; c < 2; ++c) {
            const int ch = lch0 + c;
            cp16(aB + swz(lrow, ch), Ap + ch * 8);
            cp16(bB + swz(lrow, ch), Bp + ch * 8);
        }
        asm volatile("cp.async.commit_group;" ::: "memory");
    };

    float acc[4][4][4];
#pragma unroll
    for (int i = 0; i < 4; ++i)
#pragma unroll
        for (int j = 0; j < 4; ++j)
#pragma unroll
            for (int q = 0; q < 4; ++q) acc[i][j][q] = 0.f;

    load_slab(0, 0);
    load_slab(1, 1);

    const int l16 = lane & 15, lhi = lane >> 4;      // A ldmatrix addressing
    const int l8 = lane & 7, grp = lane >> 3;        // B ldmatrix addressing

    for (int s = 0; s < total_slabs; ++s) {
        if (s + 1 >= total_slabs) asm volatile("cp.async.wait_group 0;" ::: "memory");
        else                      asm volatile("cp.async.wait_group 1;" ::: "memory");
        __syncthreads();

        const int st = s % 3;
        // prefetch 2 ahead into the buffer freed by iteration s-1
        if (s + 2 < total_slabs) load_slab((s + 2) % 3, s + 2);

        const uint32_t aB = sbase + st * 16384;
        const uint32_t bB = aB + 8192;
#pragma unroll
        for (int j = 0; j < 2; ++j) {                 // two k16 steps per slab
            uint32_t af[4][4];
#pragma unroll
            for (int mt = 0; mt < 4; ++mt) {
                const int row = wm * 64 + mt * 16 + l16;
                ldsm_x4(af[mt][0], af[mt][1], af[mt][2], af[mt][3],
                        aB + swz(row, 2 * j + lhi));
            }
            uint32_t bfr[4][2];
#pragma unroll
            for (int g = 0; g < 2; ++g) {
                const int row = wn * 32 + g * 16 + ((grp >> 1) << 3) + l8;
                uint32_t r0, r1, r2, r3;
                ldsm_x4(r0, r1, r2, r3, bB + swz(row, 2 * j + (grp & 1)));
                bfr[g * 2 + 0][0] = r0; bfr[g * 2 + 0][1] = r1;
                bfr[g * 2 + 1][0] = r2; bfr[g * 2 + 1][1] = r3;
            }
#pragma unroll
            for (int mt = 0; mt < 4; ++mt)
#pragma unroll
                for (int nt = 0; nt < 4; ++nt)
                    mma_bf16(acc[mt][nt], af[mt], bfr[nt]);
        }
    }

    // epilogue
    const int gr = lane >> 2, gc = (lane & 3) << 1;
#pragma unroll
    for (int mt = 0; mt < 4; ++mt) {
#pragma unroll
        for (int nt = 0; nt < 4; ++nt) {
            float* p0 = C + (size_t)(m0 + wm * 64 + mt * 16 + gr) * N
                         + n0 + wn * 32 + nt * 8 + gc;
            float* p1 = p0 + (size_t)8 * N;
            *(float2*)p0 = make_float2(acc[mt][nt][0], acc[mt][nt][1]);
            *(float2*)p1 = make_float2(acc[mt][nt][2], acc[mt][nt][3]);
        }
    }
}

// ---------------- transpose K/V heads: qkv -> [bh][i][t] ----------------
__global__ __launch_bounds__(256)
void transpose_kv_kernel(const float* __restrict__ qkv,
                         float* __restrict__ kt, float* __restrict__ vt)
{
    __shared__ float tile[32][33];
    const int z = blockIdx.z;
    const int sel = z & 1, bh = z >> 1;
    const int b = bh >> 4, h = bh & 15;
    const float* src = qkv + (size_t)b * Tn * 3072 + 1024 + sel * 1024 + h * 64;
    const int t0 = blockIdx.x * 32, i0 = blockIdx.y * 32;
    const int tx = threadIdx.x & 31, ty = threadIdx.x >> 5;   // 32 x 8

#pragma unroll
    for (int r = 0; r < 32; r += 8)
        tile[ty + r][tx] = src[(size_t)(t0 + ty + r) * 3072 + i0 + tx];
    __syncthreads();
    float* dst = (sel ? vt : kt) + (size_t)bh * (HSn * Tn);
#pragma unroll
    for (int r = 0; r < 32; r += 8)
        dst[(size_t)(i0 + ty + r) * Tn + t0 + tx] = tile[tx][ty + r];
}

// ---------------- Conv1d partial: 16 channels per block ----------------
__global__ __launch_bounds__(256)
void conv_partial_kernel(const float* __restrict__ kt, const float* __restrict__ vt,
                         const float* __restrict__ conv_w, float* __restrict__ partial)
{
    __shared__ float shW[64 * 33];
    __shared__ float shIn[1104];

    const int bh  = blockIdx.x;
    const int sel = blockIdx.y;
    const int ic  = blockIdx.z;          // channel chunk 0..3
    const float* base = (sel ? vt : kt) + (size_t)bh * (HSn * Tn);

    const int tid = threadIdx.x;
    const int og = tid >> 4;
    const int ng = tid & 15;

    float acc[16];
#pragma unroll
    for (int i = 0; i < 16; ++i) acc[i] = 0.f;

    for (int ii = 0; ii < 16; ++ii) {
        const int i = ic * 16 + ii;
        __syncthreads();
        for (int idx = tid; idx < 2048; idx += 256) {
            int o = idx >> 5, kk = idx & 31;
            shW[o * 33 + kk] = conv_w[((size_t)o * 64 + i) * 32 + kk];
        }
        const float* row = base + (size_t)i * Tn;
        for (int t = tid; t < 1024; t += 256)
            shIn[(t >> 4) * 17 + (t & 15)] = row[t];
        if (tid < 17) shIn[1087 + tid] = 0.f;
        __syncthreads();

#pragma unroll 4
        for (int kk = 0; kk < 32; ++kk) {
            const float w0 = shW[(og * 4 + 0) * 33 + kk];
            const float w1 = shW[(og * 4 + 1) * 33 + kk];
            const float w2 = shW[(og * 4 + 2) * 33 + kk];
            const float w3 = shW[(og * 4 + 3) * 33 + kk];
            const int hi = kk >> 4, lo = kk & 15;
#pragma unroll
            for (int q = 0; q < 4; ++q) {
                int nb = ng * 4 + q;
                float xin = shIn[(nb + hi) * 17 + lo];
                acc[0 + q]  = fmaf(w0, xin, acc[0 + q]);
                acc[4 + q]  = fmaf(w1, xin, acc[4 + q]);
                acc[8 + q]  = fmaf(w2, xin, acc[8 + q]);
                acc[12 + q] = fmaf(w3, xin, acc[12 + q]);
            }
        }
    }

    float* outp = partial + ((size_t)((bh * 2 + sel) * 4 + ic)) * (NBn * 64);
#pragma unroll
    for (int s = 0; s < 4; ++s)
#pragma unroll
        for (int q = 0; q < 4; ++q) {
            int nb = ng * 4 + q;
            if (nb < NBn) outp[nb * 64 + og * 4 + s] = acc[s * 4 + q];
        }
}

// ---------------- Conv reduce + LN(hs) + exact GELU ----------------
__global__ __launch_bounds__(256)
void conv_reduce_kernel(const float* __restrict__ partial, const float* __restrict__ ln_comp_w,
                        float* __restrict__ kc, float* __restrict__ vc)
{
    const int bh = blockIdx.x, sel = blockIdx.y;
    const float* p = partial + ((size_t)(bh * 2 + sel) * 4) * (NBn * 64);
    float* out = (sel ? vc : kc) + (size_t)bh * NBn * 64;
    const int warp = threadIdx.x >> 5, lane = threadIdx.x & 31;
    const int CS = NBn * 64;   // 4032

    for (int nb = warp; nb < NBn; nb += 8) {
        float x0 = p[nb * 64 + lane]          + p[CS + nb * 64 + lane]
                 + p[2 * CS + nb * 64 + lane] + p[3 * CS + nb * 64 + lane];
        float x1 = p[nb * 64 + 32 + lane]          + p[CS + nb * 64 + 32 + lane]
                 + p[2 * CS + nb * 64 + 32 + lane] + p[3 * CS + nb * 64 + 32 + lane];
        float sm = x0 + x1, sq = x0 * x0 + x1 * x1;
#pragma unroll
        for (int off = 16; off; off >>= 1) {
            sm += __shfl_xor_sync(0xffffffffu, sm, off);
            sq += __shfl_xor_sync(0xffffffffu, sq, off);
        }
        float mean = sm * (1.f / 64.f);
        float var  = sq * (1.f / 64.f) - mean * mean;
        float inv  = rsqrtf(var + EPSf);
        float z0 = (x0 - mean) * inv * ln_comp_w[lane];
        float z1 = (x1 - mean) * inv * ln_comp_w[32 + lane];
        out[nb * 64 + lane]      = 0.5f * z0 * (1.f + erff(z0 * 0.70710678118654752f));
        out[nb * 64 + 32 + lane] = 0.5f * z1 * (1.f + erff(z1 * 0.70710678118654752f));
    }
}

// ---------------- Local banded causal attention ----------------
#define LOC_SMEM_FLOATS (64 * 193 + 192 * 64 + 8 * 192)
__global__ __launch_bounds__(256)
void local_attn_kernel(const float* __restrict__ qkv, float* __restrict__ outp)
{
    extern __shared__ float sm[];
    float* Kt    = sm;
    float* V     = sm + 64 * 193;
    float* probs = V + 192 * 64;

    const int qtile = blockIdx.x, bh = blockIdx.y;
    const int b = bh >> 4, h = bh & 15;
    const int qstart = qtile * 64;
    const int kstart = qstart - 128;
    const float* qbase = qkv + (size_t)b * Tn * 3072 + h * 64;

    for (int idx = threadIdx.x; idx < 192 * 64; idx += 256) {
        int j = idx >> 6, d = idx & 63;
        int t = kstart + j;
        float kv = 0.f, vv = 0.f;
        if (t >= 0) {
            const float* p = qbase + (size_t)t * 3072;
            kv = p[1024 + d];
            vv = p[2048 + d];
        }
        Kt[d * 193 + j] = kv;
        V[idx] = vv;
    }
    __syncthreads();

    const int warp = threadIdx.x >> 5, lane = threadIdx.x & 31;
    const int jlo_base = (kstart < 0) ? -kstart : 0;

    for (int r = 0; r < 8; ++r) {
        const int qi = warp * 8 + r;
        const int qg = qstart + qi;
        float qreg[64];
        const float* qp = qbase + (size_t)qg * 3072;
#pragma unroll
        for (int d = 0; d < 64; ++d) qreg[d] = __ldg(qp + d);

        const int jlo = (qi > jlo_base) ? qi : jlo_base;
        const int jhi = qi + 128;

        float mx = -1e30f;
        float sv[6];
#pragma unroll
        for (int m = 0; m < 6; ++m) {
            int j = lane + 32 * m;
            float s = -1e30f;
            if (32 * m <= jhi && 32 * m + 31 >= jlo && j >= jlo && j <= jhi) {
                float a = 0.f;
#pragma unroll
                for (int d = 0; d < 64; ++d) a = fmaf(qreg[d], Kt[d * 193 + j], a);
                s = a * 0.125f;
            }
            sv[m] = s;
            mx = fmaxf(mx, s);
        }
#pragma unroll
        for (int off = 16; off; off >>= 1) mx = fmaxf(mx, __shfl_xor_sync(0xffffffffu, mx, off));

        float sum = 0.f;
#pragma unroll
        for (int m = 0; m < 6; ++m) {
            int j = lane + 32 * m;
            float p = (sv[m] > -1e29f) ? __expf(sv[m] - mx) : 0.f;
            probs[warp * 192 + j] = p;
            sum += p;
        }
#pragma unroll
        for (int off = 16; off; off >>= 1) sum += __shfl_xor_sync(0xffffffffu, sum, off);
        const float invs = 1.f / sum;
        __syncwarp();

        float a0 = 0.f, a1 = 0.f;
        const int d0 = lane * 2;
        const float* pw = probs + warp * 192;
#pragma unroll 4
        for (int j = jlo; j <= jhi; ++j) {
            float p = pw[j];
            float2 v2 = *(const float2*)&V[j * 64 + d0];
            a0 = fmaf(p, v2.x, a0);
            a1 = fmaf(p, v2.y, a1);
        }
        float* op = outp + ((size_t)(b * Tn + qg)) * Cn + h * 64 + d0;
        op[0] = a0 * invs;
        op[1] = a1 * invs;
        __syncwarp();
    }
}

// ---------------- Compressed-KV attention ----------------
__global__ __launch_bounds__(256)
void comp_attn_kernel(const float* __restrict__ qkv, const float* __restrict__ kc,
                      const float* __restrict__ vc, float* __restrict__ outp)
{
    __shared__ float Kct[64 * 64];
    __shared__ float Vc[63 * 64];
    __shared__ float probs[8 * 64];

    const int bh = blockIdx.y;
    const int b = bh >> 4, h = bh & 15;
    const int qstart = blockIdx.x * 128;

    for (int idx = threadIdx.x; idx < 63 * 64; idx += 256) {
        int j = idx >> 6, d = idx & 63;
        Kct[d * 64 + j] = kc[(size_t)bh * 63 * 64 + idx];
        Vc[idx]         = vc[(size_t)bh * 63 * 64 + idx];
    }
    __syncthreads();

    const int warp = threadIdx.x >> 5, lane = threadIdx.x & 31;
    const float* qbase = qkv + (size_t)b * Tn * 3072 + h * 64;

    for (int r = 0; r < 16; ++r) {
        const int qg = qstart + warp * 16 + r;
        const int nk = (qg < 62 ? qg : 62) + 1;
        float qreg[64];
        const float* qp = qbase + (size_t)qg * 3072;
#pragma unroll
        for (int d = 0; d < 64; ++d) qreg[d] = __ldg(qp + d);

        float mx = -1e30f;
        float sv[2];
#pragma unroll
        for (int m = 0; m < 2; ++m) {
            int j = lane + 32 * m;
            float s = -1e30f;
            if (j < nk) {
                float a = 0.f;
#pragma unroll
                for (int d = 0; d < 64; ++d) a = fmaf(qreg[d], Kct[d * 64 + j], a);
                s = a * 0.125f;
            }
            sv[m] = s;
            mx = fmaxf(mx, s);
        }
#pragma unroll
        for (int off = 16; off; off >>= 1) mx = fmaxf(mx, __shfl_xor_sync(0xffffffffu, mx, off));
        float sum = 0.f;
#pragma unroll
        for (int m = 0; m < 2; ++m) {
            int j = lane + 32 * m;
            float p = (sv[m] > -1e29f) ? __expf(sv[m] - mx) : 0.f;
            probs[warp * 64 + j] = p;
            sum += p;
        }
#pragma unroll
        for (int off = 16; off; off >>= 1) sum += __shfl_xor_sync(0xffffffffu, sum, off);
        const float invs = 1.f / sum;
        __syncwarp();

        float a0 = 0.f, a1 = 0.f;
        const int d0 = lane * 2;
        const float* pw = probs + warp * 64;
        for (int j = 0; j < nk; ++j) {
            float p = pw[j];
            float2 v2 = *(const float2*)&Vc[j * 64 + d0];
            a0 = fmaf(p, v2.x, a0);
            a1 = fmaf(p, v2.y, a1);
        }
        float* op = outp + ((size_t)(b * Tn + qg)) * Cn + h * 64 + d0;
        op[0] = a0 * invs;
        op[1] = a1 * invs;
        __syncwarp();
    }
}

// ---------------- In-place row LayerNorm over C=1024 ----------------
__global__ __launch_bounds__(256)
void ln_rows_kernel(float* __restrict__ buf, const float* __restrict__ w)
{
    __shared__ float rs[8], rq[8], fin[2];
    const size_t row = blockIdx.x;
    float* p = buf + row * 1024;
    float x[4];
    float sm = 0.f, sq = 0.f;
#pragma unroll
    for (int k = 0; k < 4; ++k) {
        x[k] = p[threadIdx.x + k * 256];
        sm += x[k]; sq += x[k] * x[k];
    }
    const int warp = threadIdx.x >> 5, lane = threadIdx.x & 31;
#pragma unroll
    for (int off = 16; off; off >>= 1) {
        sm += __shfl_xor_sync(0xffffffffu, sm, off);
        sq += __shfl_xor_sync(0xffffffffu, sq, off);
    }
    if (lane == 0) { rs[warp] = sm; rq[warp] = sq; }
    __syncthreads();
    if (threadIdx.x == 0) {
        float a = 0.f, c = 0.f;
#pragma unroll
        for (int i = 0; i < 8; ++i) { a += rs[i]; c += rq[i]; }
        float mean = a * (1.f / 1024.f);
        float var  = c * (1.f / 1024.f) - mean * mean;
        fin[0] = mean;
        fin[1] = rsqrtf(var + EPSf);
    }
    __syncthreads();
    const float mean = fin[0], inv = fin[1];
#pragma unroll
    for (int k = 0; k < 4; ++k) {
        int c = threadIdx.x + k * 256;
        p[c] = (x[k] - mean) * inv * w[c];
    }
}

// ---------------- Gating MLP (one block per batch) ----------------
__global__ __launch_bounds__(256)
void gate_kernel(const float* __restrict__ localn, const float* __restrict__ comp,
                 const float* __restrict__ w1, const float* __restrict__ lnw,
                 const float* __restrict__ w2, float* __restrict__ gates)
{
    __shared__ float feats[2048];
    __shared__ float hsh[1024];
    __shared__ float rs[8], rq[8], fin[2];
    __shared__ float rl0[8], rl1[8];

    const int b = blockIdx.x;
    for (int idx = threadIdx.x; idx < 1024; idx += 256) {
        feats[idx]        = localn[((size_t)b * Tn + 1023) * Cn + idx];
        feats[1024 + idx] = comp  [((size_t)b * Tn + 1023) * Cn + idx];
    }
    __syncthreads();

#pragma unroll
    for (int jj = 0; jj < 4; ++jj) {
        int j = jj * 256 + threadIdx.x;
        const float4* wr = (const float4*)(w1 + (size_t)j * 2048);
        float a = 0.f;
        for (int c4 = 0; c4 < 512; ++c4) {
            float4 wv = __ldg(wr + c4);
            float4 fv = *(const float4*)&feats[c4 * 4];
            a += wv.x * fv.x + wv.y * fv.y + wv.z * fv.z + wv.w * fv.w;
        }
        hsh[j] = a;
    }
    __syncthreads();

    float sm = 0.f, sq = 0.f;
#pragma unroll
    for (int jj = 0; jj < 4; ++jj) {
        float v = hsh[jj * 256 + threadIdx.x];
        sm += v; sq += v * v;
    }
    const int warp = threadIdx.x >> 5, lane = threadIdx.x & 31;
#pragma unroll
    for (int off = 16; off; off >>= 1) {
        sm += __shfl_xor_sync(0xffffffffu, sm, off);
        sq += __shfl_xor_sync(0xffffffffu, sq, off);
    }
    if (lane == 0) { rs[warp] = sm; rq[warp] = sq; }
    __syncthreads();
    if (threadIdx.x == 0) {
        float a = 0.f, c = 0.f;
#pragma unroll
        for (int i = 0; i < 8; ++i) { a += rs[i]; c += rq[i]; }
        float mean = a * (1.f / 1024.f);
        float var  = c * (1.f / 1024.f) - mean * mean;
        fin[0] = mean;
        fin[1] = rsqrtf(var + EPSf);
    }
    __syncthreads();
    const float mean = fin[0], inv = fin[1];

    float l0 = 0.f, l1 = 0.f;
#pragma unroll
    for (int jj = 0; jj < 4; ++jj) {
        int j = jj * 256 + threadIdx.x;
        float hp = (hsh[j] - mean) * inv * lnw[j];
        hp = fmaxf(hp, 0.f);
        l0 = fmaf(hp, w2[j], l0);
        l1 = fmaf(hp, w2[1024 + j], l1);
    }
#pragma unroll
    for (int off = 16; off; off >>= 1) {
        l0 += __shfl_xor_sync(0xffffffffu, l0, off);
        l1 += __shfl_xor_sync(0xffffffffu, l1, off);
    }
    if (lane == 0) { rl0[warp] = l0; rl1[warp] = l1; }
    __syncthreads();
    if (threadIdx.x == 0) {
        float a = 0.f, c = 0.f;
#pragma unroll
        for (int i = 0; i < 8; ++i) { a += rl0[i]; c += rl1[i]; }
        float m = fmaxf(a, c);
        float e0 = __expf(a - m), e1 = __expf(c - m);
        float s = e0 + e1;
        gates[2 * b]     = e0 / s;
        gates[2 * b + 1] = e1 / s;
    }
}

// ---------------- Gated combination ----------------
__global__ __launch_bounds__(256)
void combine_kernel(const float* __restrict__ ln, const float* __restrict__ cp,
                    const float* __restrict__ gates, float* __restrict__ out)
{
    const int idx = blockIdx.x * 256 + threadIdx.x;
    const int b = idx >> 18;
    const float g0 = gates[2 * b], g1 = gates[2 * b + 1];
    float4 a = ((const float4*)ln)[idx];
    float4 c = ((const float4*)cp)[idx];
    ((float4*)out)[idx] = make_float4(g0 * a.x + g1 * c.x, g0 * a.y + g1 * c.y,
                                      g0 * a.z + g1 * c.z, g0 * a.w + g1 * c.w);
}

// ---------------- launch ----------------
extern "C" void kernel_launch(void* const* d_in, const int* in_sizes, int n_in,
                              void* d_out, int out_size)
{
    const float* x          = (const float*)d_in[0];
    const float* c_attn_w   = (const float*)d_in[1];
    const float* conv_w     = (const float*)d_in[2];
    const float* ln_comp_w  = (const float*)d_in[3];
    const float* ln_local_w = (const float*)d_in[4];
    const float* gate_w1    = (const float*)d_in[5];
    const float* gate_ln_w  = (const float*)d_in[6];
    const float* gate_w2    = (const float*)d_in[7];
    const float* c_proj_w   = (const float*)d_in[8];
    float* y = (float*)d_out;

    float *qkv, *kc, *vc, *loc, *cmp, *comb, *gates, *kt, *vt, *convp;
    __nv_bfloat16 *ah, *al, *bh, *bl;
    cudaGetSymbolAddress((void**)&qkv,   g_qkv);
    cudaGetSymbolAddress((void**)&kc,    g_kc);
    cudaGetSymbolAddress((void**)&vc,    g_vc);
    cudaGetSymbolAddress((void**)&loc,   g_loc);
    cudaGetSymbolAddress((void**)&cmp,   g_cmp);
    cudaGetSymbolAddress((void**)&comb,  g_comb);
    cudaGetSymbolAddress((void**)&gates, g_gates);
    cudaGetSymbolAddress((void**)&kt,    g_kt);
    cudaGetSymbolAddress((void**)&vt,    g_vt);
    cudaGetSymbolAddress((void**)&convp, g_convp);
    cudaGetSymbolAddress((void**)&ah,    g_ah);
    cudaGetSymbolAddress((void**)&al,    g_al);
    cudaGetSymbolAddress((void**)&bh,    g_bh);
    cudaGetSymbolAddress((void**)&bl,    g_bl);

    cudaFuncSetAttribute(local_attn_kernel, cudaFuncAttributeMaxDynamicSharedMemorySize,
                         LOC_SMEM_FLOATS * (int)sizeof(float));
    cudaFuncSetAttribute(gemm_bf16_mma, cudaFuncAttributeMaxDynamicSharedMemorySize,
                         GEMM_SMEM_BYTES);

    const int nX  = Bn * Tn * Cn;       // 8M
    const int nW1 = 3 * Cn * Cn;        // 3M
    const int nW2 = Cn * Cn;            // 1M

    // 1) split inputs + c_attn weights to bf16 hi/lo
    split_bf16_kernel<<<(nX / 4 + 255) / 256, 256>>>((const float4*)x,
        (__nv_bfloat162*)ah, (__nv_bfloat162*)al, nX / 4);
    split_bf16_kernel<<<(nW1 / 4 + 255) / 256, 256>>>((const float4*)c_attn_w,
        (__nv_bfloat162*)bh, (__nv_bfloat162*)bl, nW1 / 4);
    // 2) QKV projection on tensor cores (mma.sync): [8192,3072]
    gemm_bf16_mma<<<dim3(3072 / 128, 8192 / 128), 256, GEMM_SMEM_BYTES>>>(
        ah, al, bh, bl, qkv, 3072, 1024);
    // 3) transpose K/V heads for coalesced conv input
    transpose_kv_kernel<<<dim3(Tn / 32, HSn / 32, Bn * Hn * 2), 256>>>(qkv, kt, vt);
    // 4) conv partials (4 channel-chunks) + reduce with LN/GELU
    conv_partial_kernel<<<dim3(Bn * Hn, 2, 4), 256>>>(kt, vt, conv_w, convp);
    conv_reduce_kernel<<<dim3(Bn * Hn, 2), 256>>>(convp, ln_comp_w, kc, vc);
    // 5) local banded attention -> g_loc
    local_attn_kernel<<<dim3(Tn / 64, Bn * Hn), 256, LOC_SMEM_FLOATS * sizeof(float)>>>(qkv, loc);
    // 6) in-place LN over C on local output
    ln_rows_kernel<<<Bn * Tn, 256>>>(loc, ln_local_w);
    // 7) compressed attention -> g_cmp
    comp_attn_kernel<<<dim3(Tn / 128, Bn * Hn), 256>>>(qkv, kc, vc, cmp);
    // 8) gating from last-token features
    gate_kernel<<<Bn, 256>>>(loc, cmp, gate_w1, gate_ln_w, gate_w2, gates);
    // 9) gated combine
    combine_kernel<<<(Bn * Tn * Cn / 4) / 256, 256>>>(loc, cmp, gates, comb);
    // 10) split combined + c_proj weights, output projection on tensor cores
    split_bf16_kernel<<<(nX / 4 + 255) / 256, 256>>>((const float4*)comb,
        (__nv_bfloat162*)ah, (__nv_bfloat162*)al, nX / 4);
    split_bf16_kernel<<<(nW2 / 4 + 255) / 256, 256>>>((const float4*)c_proj_w,
        (__nv_bfloat162*)bh, (__nv_bfloat162*)bl, nW2 / 4);
    gemm_bf16_mma<<<dim3(1024 / 128, 8192 / 128), 256, GEMM_SMEM_BYTES>>>(
        ah, al, bh, bl, y, 1024, 1024);
}